// round 17
// baseline (speedup 1.0000x reference)
#include <cuda_runtime.h>
#include <cuda_fp16.h>
#include <math.h>

#define N_NODES 10000
#define N_EDGES 160000
#define CDIM 128
#define ADIM 10
#define RDIM 8
#define HDIM 64
#define NPAD 10688

#define INV_SQRT_R 0.35355339059327373f
#define INV_SQRT_H 0.125f
#define INV_SQRT_C 0.08838834764831845f
#define INV_SQRT3  0.5773502691896258f
// 1 / (sqrt(2C)*AVG_NEI * sqrt(C*A)) = 1/(256 * sqrt(1280))
#define OUT_SCALE  (1.0f / (256.0f * 35.77708763999664f))

// ---------------- scratch (device globals; no allocations) ----------------
__device__ __half g_h16[N_EDGES * HDIM];              // 20 MB (fp16 edge MLP out)
__device__ __half g_W4T16[512 * 64];                  // 64 KB (W4 transposed, fp16)
__device__ __half g_W2T16[64 * 64];
__device__ __half g_W3T16[64 * 64];
__device__ __half g_tpw16[(size_t)N_EDGES * 512];     // 163 MB (fp16 tp_w, CSR order)
__device__ float g_s[N_NODES * CDIM];                 // 5 MB
__device__ float g_v[N_NODES * CDIM * 3];             // 15 MB, planar [n][comp][128]
__device__ __half g_M16[4 * N_NODES * 256];           // 20 MB (fp16 M planes)
__device__ __half g_WcT0[ADIM * 128 * 256];           // 640 KB (fused W, transposed fp16)
__device__ __half g_WcT1[ADIM * 128 * 256];           // 640 KB
__device__ int    g_cnt[N_NODES];
__device__ int    g_off[N_NODES + 1];
__device__ int    g_cur[N_NODES];
__device__ int    g_pos[N_EDGES];                     // edge -> CSR slot
__device__ int    g_scsr[N_EDGES];                    // CSR-ordered sender
__device__ float4 g_eacsr[N_EDGES];                   // CSR-ordered edge_attrs
__device__ int    g_cls[N_NODES];
__device__ int    g_pcoff[ADIM + 1];
__device__ int    g_ccur[ADIM];
__device__ int    g_clistp[NPAD];

// fast silu: MUFU-based exp + approx divide (rel err ~1e-6, fine vs 1e-3 gate)
__device__ __forceinline__ float silu(float x) {
    float e = __expf(-x);
    return __fdividef(x, 1.0f + e);
}

__device__ __forceinline__ unsigned smem_u32(const void* p) {
    unsigned a;
    asm("{ .reg .u64 t; cvta.to.shared.u64 t, %1; cvt.u32.u64 %0, t; }" : "=r"(a) : "l"(p));
    return a;
}

#define LDSM4(r0, r1, r2, r3, addr) \
    asm volatile("ldmatrix.sync.aligned.m8n8.x4.shared.b16 {%0,%1,%2,%3}, [%4];" \
        : "=r"(r0), "=r"(r1), "=r"(r2), "=r"(r3) : "r"(addr))

#define MMA16816(acc, a0, a1, a2, a3, b0, b1) \
    asm volatile("mma.sync.aligned.m16n8k16.row.col.f32.f16.f16.f32 " \
        "{%0,%1,%2,%3}, {%4,%5,%6,%7}, {%8,%9}, {%0,%1,%2,%3};" \
        : "+f"((acc)[0]), "+f"((acc)[1]), "+f"((acc)[2]), "+f"((acc)[3]) \
        : "r"(a0), "r"(a1), "r"(a2), "r"(a3), "r"(b0), "r"(b1))

// ---------------- plumbing ----------------
__global__ void k_cls(const float* __restrict__ na) {
    int n = blockIdx.x * 256 + threadIdx.x;
    if (n < NPAD) g_clistp[n] = -1;
    if (n >= N_NODES) return;
    g_cnt[n] = 0;
    int a = 0;
    #pragma unroll
    for (int j = 0; j < ADIM; j++)
        if (na[n * ADIM + j] > 0.5f) a = j;
    g_cls[n] = a;
}

__global__ void k_count(const int* __restrict__ recv) {
    int e = blockIdx.x * 256 + threadIdx.x;   // E % 256 == 0
    atomicAdd(&g_cnt[recv[e]], 1);
}

__global__ void k_scan() {
    __shared__ int sp[1024];
    __shared__ int bins[ADIM];
    int t = threadIdx.x;
    if (t < ADIM) bins[t] = 0;
    __syncthreads();
    const int PER = 10;
    int base = t * PER;
    int loc[PER];
    int sum = 0;
    #pragma unroll
    for (int j = 0; j < PER; j++) {
        int idx = base + j;
        int v = 0;
        if (idx < N_NODES) {
            v = g_cnt[idx];
            atomicAdd(&bins[g_cls[idx]], 1);
        }
        loc[j] = sum; sum += v;
    }
    sp[t] = sum;
    __syncthreads();
    for (int d = 1; d < 1024; d <<= 1) {
        int v = (t >= d) ? sp[t - d] : 0;
        __syncthreads();
        sp[t] += v;
        __syncthreads();
    }
    int off = (t > 0) ? sp[t - 1] : 0;
    #pragma unroll
    for (int j = 0; j < PER; j++) {
        int idx = base + j;
        if (idx < N_NODES) { int o = off + loc[j]; g_off[idx] = o; g_cur[idx] = o; }
    }
    if (t == 0) {
        g_off[N_NODES] = sp[1023];
        int pc = 0;
        for (int a = 0; a < ADIM; a++) {
            g_pcoff[a] = pc; g_ccur[a] = pc;
            pc += ((bins[a] + 63) >> 6) << 6;     // pad each class to 64-row tiles
        }
        g_pcoff[ADIM] = pc;
    }
}

// builds CSR slot map + CSR-permuted sender/edge_attrs + class list
__global__ void k_fill(const int* __restrict__ recv, const int* __restrict__ sender,
                       const float* __restrict__ ea) {
    int i = blockIdx.x * 256 + threadIdx.x;
    if (i < N_EDGES) {
        int r = recv[i];
        int p = atomicAdd(&g_cur[r], 1);
        g_pos[i] = p;
        g_scsr[p] = sender[i];
        g_eacsr[p] = *(const float4*)&ea[i * 4];
    }
    if (i < N_NODES) {
        int a = g_cls[i];
        int p = atomicAdd(&g_ccur[a], 1);
        g_clistp[p] = i;
    }
}

// ---------------- weight transposes to fp16 (one-shot tiny kernel) ----------------
__global__ void k_w4t(const float* __restrict__ W4, const float* __restrict__ W2,
                      const float* __restrict__ W3) {
    int gid = blockIdx.x * 256 + threadIdx.x;
    if (gid < 64 * 512) {
        int k = gid >> 9, n = gid & 511;
        g_W4T16[n * 64 + k] = __float2half_rn(W4[gid]);
    }
    int r = gid - 64 * 512;
    if (r >= 0 && r < 64 * 64) {
        int k = r >> 6, n = r & 63;
        g_W2T16[n * 64 + k] = __float2half_rn(W2[r]);
        g_W3T16[n * 64 + k] = __float2half_rn(W3[r]);
    }
}

// ---------------- edge MLP: 8 -> 64 (scalar) -> 64 -> 64 (fp16 mma) ----------------
// (verified R15 version, unchanged)
__global__ __launch_bounds__(128) void k_mlp(const float* __restrict__ ef,
                                             const float* __restrict__ W1) {
    __shared__ float sW1[RDIM * HDIM];
    __shared__ __align__(16) unsigned sA[64 * 36];
    __shared__ __align__(16) unsigned sC[64 * 36];
    __shared__ __align__(16) unsigned sB[64 * 36];
    unsigned sbA = smem_u32(sA), sbC = smem_u32(sC), sbB = smem_u32(sB);

    int t = threadIdx.x, lane = t & 31, wid = t >> 5;
    int e0 = blockIdx.x * 64;                 // E = 2500 * 64

    for (int i = t; i < RDIM * HDIM; i += 128) sW1[i] = W1[i];
    for (int i = t; i < 64 * 8; i += 128) {
        int n = i >> 3, u = i & 7;
        uint4 v = ((const uint4*)g_W2T16)[n * 8 + u];
        *(uint4*)&sB[n * 36 + u * 4] = v;
    }
    __syncthreads();

    // ---- layer 1 (scalar): 2 threads per edge, 32 outs each ----
    {
        int e1 = t >> 1, oh = t & 1;
        const float4* xf = (const float4*)&ef[(size_t)(e0 + e1) * 8];
        float4 xa = xf[0], xb = xf[1];
        float x[8] = {xa.x, xa.y, xa.z, xa.w, xb.x, xb.y, xb.z, xb.w};
        #pragma unroll
        for (int j = 0; j < 16; j++) {
            float a0 = 0.f, a1 = 0.f;
            #pragma unroll
            for (int k = 0; k < 8; k++) {
                float xv = x[k];
                a0 = fmaf(xv, sW1[k * 64 + oh * 32 + 2 * j], a0);
                a1 = fmaf(xv, sW1[k * 64 + oh * 32 + 2 * j + 1], a1);
            }
            __half2 p = __floats2half2_rn(silu(a0 * INV_SQRT_R), silu(a1 * INV_SQRT_R));
            sA[e1 * 36 + oh * 16 + j] = *(unsigned*)&p;
        }
    }
    __syncthreads();

    int g = lane >> 2, q = lane & 3;
    int m0 = (wid >> 1) * 32;
    int n0 = (wid & 1) * 32;
    unsigned aoff = (unsigned)((lane & 15) * 144 + ((lane >> 4) << 4)) + m0 * 144;
    unsigned boff = (unsigned)((((lane >> 4) << 3) + (lane & 7)) * 144 + (((lane >> 3) & 1) << 4)) + n0 * 144;

    // ---- layer 2 mma ----
    {
        float acc[2][4][4];
        #pragma unroll
        for (int mt = 0; mt < 2; mt++)
            #pragma unroll
            for (int nt = 0; nt < 4; nt++)
                #pragma unroll
                for (int j = 0; j < 4; j++) acc[mt][nt][j] = 0.f;
        #pragma unroll
        for (int kt = 0; kt < 4; kt++) {
            unsigned a[2][4];
            #pragma unroll
            for (int mt = 0; mt < 2; mt++)
                LDSM4(a[mt][0], a[mt][1], a[mt][2], a[mt][3], sbA + aoff + mt * 2304 + kt * 32);
            #pragma unroll
            for (int j = 0; j < 2; j++) {
                unsigned b[4];
                LDSM4(b[0], b[1], b[2], b[3], sbB + boff + j * 2304 + kt * 32);
                #pragma unroll
                for (int h = 0; h < 2; h++) {
                    int nt = j * 2 + h;
                    #pragma unroll
                    for (int mt = 0; mt < 2; mt++)
                        MMA16816(acc[mt][nt], a[mt][0], a[mt][1], a[mt][2], a[mt][3],
                                 b[h * 2], b[h * 2 + 1]);
                }
            }
        }
        #pragma unroll
        for (int mt = 0; mt < 2; mt++) {
            int r = m0 + mt * 16 + g;
            #pragma unroll
            for (int nt = 0; nt < 4; nt++) {
                int colw = (n0 + nt * 8 + q * 2) >> 1;
                __half2 d0 = __floats2half2_rn(silu(acc[mt][nt][0] * INV_SQRT_H),
                                               silu(acc[mt][nt][1] * INV_SQRT_H));
                __half2 d1 = __floats2half2_rn(silu(acc[mt][nt][2] * INV_SQRT_H),
                                               silu(acc[mt][nt][3] * INV_SQRT_H));
                sC[r * 36 + colw]       = *(unsigned*)&d0;
                sC[(r + 8) * 36 + colw] = *(unsigned*)&d1;
            }
        }
    }
    __syncthreads();
    for (int i = t; i < 64 * 8; i += 128) {
        int n = i >> 3, u = i & 7;
        uint4 v = ((const uint4*)g_W3T16)[n * 8 + u];
        *(uint4*)&sB[n * 36 + u * 4] = v;
    }
    __syncthreads();

    // ---- layer 3 mma ----
    {
        float acc[2][4][4];
        #pragma unroll
        for (int mt = 0; mt < 2; mt++)
            #pragma unroll
            for (int nt = 0; nt < 4; nt++)
                #pragma unroll
                for (int j = 0; j < 4; j++) acc[mt][nt][j] = 0.f;
        #pragma unroll
        for (int kt = 0; kt < 4; kt++) {
            unsigned a[2][4];
            #pragma unroll
            for (int mt = 0; mt < 2; mt++)
                LDSM4(a[mt][0], a[mt][1], a[mt][2], a[mt][3], sbC + aoff + mt * 2304 + kt * 32);
            #pragma unroll
            for (int j = 0; j < 2; j++) {
                unsigned b[4];
                LDSM4(b[0], b[1], b[2], b[3], sbB + boff + j * 2304 + kt * 32);
                #pragma unroll
                for (int h = 0; h < 2; h++) {
                    int nt = j * 2 + h;
                    #pragma unroll
                    for (int mt = 0; mt < 2; mt++)
                        MMA16816(acc[mt][nt], a[mt][0], a[mt][1], a[mt][2], a[mt][3],
                                 b[h * 2], b[h * 2 + 1]);
                }
            }
        }
        #pragma unroll
        for (int mt = 0; mt < 2; mt++) {
            int er = e0 + m0 + mt * 16 + g;
            #pragma unroll
            for (int nt = 0; nt < 4; nt++) {
                int col = n0 + nt * 8 + q * 2;
                __half2 d0 = __floats2half2_rn(silu(acc[mt][nt][0] * INV_SQRT_H),
                                               silu(acc[mt][nt][1] * INV_SQRT_H));
                __half2 d1 = __floats2half2_rn(silu(acc[mt][nt][2] * INV_SQRT_H),
                                               silu(acc[mt][nt][3] * INV_SQRT_H));
                *(__half2*)&g_h16[(size_t)er * 64 + col]       = d0;
                *(__half2*)&g_h16[(size_t)(er + 8) * 64 + col] = d1;
            }
        }
    }
}

// ---------------- tp_w = h @ W4 / sqrt(H), rows stored at CSR slots ----------------
__global__ __launch_bounds__(128) void k_tpw() {
    __shared__ __align__(16) unsigned sA[64 * 36];    // 9216 B
    __shared__ __align__(16) unsigned sB[128 * 36];   // 18432 B (reused as 64x68 stage)
    __shared__ int sPos[64];
    unsigned sbA = smem_u32(sA), sbB = smem_u32(sB);

    int t = threadIdx.x, lane = t & 31, wid = t >> 5;
    int e0 = blockIdx.x * 64;                 // E = 2500 * 64

    if (t < 64) sPos[t] = g_pos[e0 + t];
    for (int i = t; i < 64 * 8; i += 128) {
        int row = i >> 3, u = i & 7;
        uint4 v = ((const uint4*)g_h16)[(size_t)(e0 + row) * 8 + u];
        *(uint4*)&sA[row * 36 + u * 4] = v;
    }

    int g = lane >> 2, q = lane & 3;
    int m0 = (wid >> 1) * 32;
    int n0 = (wid & 1) * 64;

    unsigned aoff = (unsigned)((lane & 15) * 144 + ((lane >> 4) << 4)) + m0 * 144;
    unsigned boff = (unsigned)((((lane >> 4) << 3) + (lane & 7)) * 144 + (((lane >> 3) & 1) << 4)) + n0 * 144;
    unsigned Ab = sbA + aoff;
    unsigned Bb = sbB + boff;

    for (int nh = 0; nh < 4; nh++) {
        __syncthreads();
        for (int i = t; i < 128 * 8; i += 128) {
            int n = i >> 3, u = i & 7;
            uint4 v = ((const uint4*)g_W4T16)[(nh * 128 + n) * 8 + u];
            *(uint4*)&sB[n * 36 + u * 4] = v;
        }
        __syncthreads();

        float acc[2][8][4];
        #pragma unroll
        for (int mt = 0; mt < 2; mt++)
            #pragma unroll
            for (int nt = 0; nt < 8; nt++)
                #pragma unroll
                for (int j = 0; j < 4; j++) acc[mt][nt][j] = 0.f;

        #pragma unroll
        for (int kt = 0; kt < 4; kt++) {
            unsigned a[2][4];
            #pragma unroll
            for (int mt = 0; mt < 2; mt++)
                LDSM4(a[mt][0], a[mt][1], a[mt][2], a[mt][3], Ab + mt * 2304 + kt * 32);
            #pragma unroll
            for (int j = 0; j < 4; j++) {
                unsigned b[4];
                LDSM4(b[0], b[1], b[2], b[3], Bb + j * 2304 + kt * 32);
                #pragma unroll
                for (int h = 0; h < 2; h++) {
                    int nt = j * 2 + h;
                    #pragma unroll
                    for (int mt = 0; mt < 2; mt++)
                        MMA16816(acc[mt][nt], a[mt][0], a[mt][1], a[mt][2], a[mt][3],
                                 b[h * 2], b[h * 2 + 1]);
                }
            }
        }

        __syncthreads();
        #pragma unroll
        for (int mt = 0; mt < 2; mt++) {
            int r = m0 + mt * 16 + g;
            #pragma unroll
            for (int nt = 0; nt < 8; nt++) {
                int colw = (n0 + nt * 8 + q * 2) >> 1;
                __half2 d0 = __floats2half2_rn(acc[mt][nt][0] * INV_SQRT_H,
                                               acc[mt][nt][1] * INV_SQRT_H);
                __half2 d1 = __floats2half2_rn(acc[mt][nt][2] * INV_SQRT_H,
                                               acc[mt][nt][3] * INV_SQRT_H);
                sB[r * 68 + colw]       = *(unsigned*)&d0;
                sB[(r + 8) * 68 + colw] = *(unsigned*)&d1;
            }
        }
        __syncthreads();
        #pragma unroll
        for (int it = 0; it < 8; it++) {
            int r = wid * 16 + it * 2 + (lane >> 4);
            int cw = lane & 15;
            uint4 v = *(uint4*)&sB[r * 68 + cw * 4];
            *(uint4*)&g_tpw16[(size_t)sPos[r] * 512 + nh * 128 + cw * 8] = v;
        }
    }
}

// ---------------- node up-projections s, v (planar v output; verified R15) ----------------
__global__ __launch_bounds__(256) void k_sv(const float* __restrict__ nf,
                                            const float* __restrict__ Wu0,
                                            const float* __restrict__ Wu1) {
    __shared__ float sW[64 * 128];   // 32 KB
    __shared__ float sX[3 * 32 * 64]; // 24 KB (y=0 uses first plane)
    int t = threadIdx.x;
    int grp = blockIdx.y;            // 0: s, 1: v(3 comps)
    int n0 = blockIdx.x * 32;
    const float* W = (grp == 0) ? Wu0 : Wu1;
    int nb = (t >> 5) << 2, ob = (t & 31) << 2;

    if (grp == 0) {
        float acc[4][4] = {};
        for (int k0 = 0; k0 < CDIM; k0 += 64) {
            __syncthreads();
            for (int i = t; i < 64 * 128; i += 256) {
                int kk = i >> 7, d = i & 127;
                sW[i] = W[(k0 + kk) * 128 + d];
            }
            for (int i = t; i < 32 * 64; i += 256) {
                int r = i >> 6, kk = i & 63;
                int n = n0 + r;
                sX[i] = (n < N_NODES) ? nf[n * 512 + k0 + kk] : 0.f;
            }
            __syncthreads();
            #pragma unroll
            for (int kk = 0; kk < 64; kk++) {
                float a0 = sX[(nb + 0) * 64 + kk];
                float a1 = sX[(nb + 1) * 64 + kk];
                float a2 = sX[(nb + 2) * 64 + kk];
                float a3 = sX[(nb + 3) * 64 + kk];
                float4 w = *(const float4*)&sW[kk * 128 + ob];
                acc[0][0] += a0 * w.x; acc[0][1] += a0 * w.y; acc[0][2] += a0 * w.z; acc[0][3] += a0 * w.w;
                acc[1][0] += a1 * w.x; acc[1][1] += a1 * w.y; acc[1][2] += a1 * w.z; acc[1][3] += a1 * w.w;
                acc[2][0] += a2 * w.x; acc[2][1] += a2 * w.y; acc[2][2] += a2 * w.z; acc[2][3] += a2 * w.w;
                acc[3][0] += a3 * w.x; acc[3][1] += a3 * w.y; acc[3][2] += a3 * w.z; acc[3][3] += a3 * w.w;
            }
        }
        #pragma unroll
        for (int r = 0; r < 4; r++) {
            int n = n0 + nb + r;
            if (n >= N_NODES) continue;
            *(float4*)&g_s[n * 128 + ob] =
                make_float4(acc[r][0] * INV_SQRT_C, acc[r][1] * INV_SQRT_C,
                            acc[r][2] * INV_SQRT_C, acc[r][3] * INV_SQRT_C);
        }
    } else {
        float acc[3][4][4] = {};
        for (int k0 = 0; k0 < CDIM; k0 += 64) {
            __syncthreads();
            for (int i = t; i < 64 * 128; i += 256) {
                int kk = i >> 7, d = i & 127;
                sW[i] = W[(k0 + kk) * 128 + d];
            }
            for (int i = t; i < 32 * 192; i += 256) {
                int n = i / 192, j = i % 192;
                int kk = j / 3, cm = j % 3;
                int node = n0 + n;
                float v = (node < N_NODES) ? nf[node * 512 + 128 + 3 * k0 + j] : 0.f;
                sX[cm * 2048 + n * 64 + kk] = v;
            }
            __syncthreads();
            #pragma unroll
            for (int kk = 0; kk < 64; kk++) {
                float4 w = *(const float4*)&sW[kk * 128 + ob];
                #pragma unroll
                for (int cm = 0; cm < 3; cm++) {
                    const float* xp = &sX[cm * 2048];
                    float a0 = xp[(nb + 0) * 64 + kk];
                    float a1 = xp[(nb + 1) * 64 + kk];
                    float a2 = xp[(nb + 2) * 64 + kk];
                    float a3 = xp[(nb + 3) * 64 + kk];
                    acc[cm][0][0] += a0 * w.x; acc[cm][0][1] += a0 * w.y; acc[cm][0][2] += a0 * w.z; acc[cm][0][3] += a0 * w.w;
                    acc[cm][1][0] += a1 * w.x; acc[cm][1][1] += a1 * w.y; acc[cm][1][2] += a1 * w.z; acc[cm][1][3] += a1 * w.w;
                    acc[cm][2][0] += a2 * w.x; acc[cm][2][1] += a2 * w.y; acc[cm][2][2] += a2 * w.z; acc[cm][2][3] += a2 * w.w;
                    acc[cm][3][0] += a3 * w.x; acc[cm][3][1] += a3 * w.y; acc[cm][3][2] += a3 * w.z; acc[cm][3][3] += a3 * w.w;
                }
            }
        }
        #pragma unroll
        for (int cm = 0; cm < 3; cm++)
            #pragma unroll
            for (int r = 0; r < 4; r++) {
                int n = n0 + nb + r;
                if (n >= N_NODES) continue;
                *(float4*)&g_v[n * 384 + cm * 128 + ob] =
                    make_float4(acc[cm][r][0] * INV_SQRT_C, acc[cm][r][1] * INV_SQRT_C,
                                acc[cm][r][2] * INV_SQRT_C, acc[cm][r][3] * INV_SQRT_C);
            }
    }
}

// ---------------- fused weights: WcT[a][col][k] = (W_lin @ W_skip[:,a,:])^T, fp16 ----------------
__global__ __launch_bounds__(256) void k_wc(const float* __restrict__ Wl0,
                                            const float* __restrict__ Wl1,
                                            const float* __restrict__ Wsk0,
                                            const float* __restrict__ Wsk1) {
    __shared__ float sSk[64 * 128];  // 32 KB
    __shared__ float sWl[16 * 64];   // 4 KB
    int t = threadIdx.x;
    int c0 = blockIdx.x * 16;
    int a = blockIdx.y;
    int pair = blockIdx.z;
    const float* Wl  = pair ? Wl1  : Wl0;
    const float* Wsk = pair ? Wsk1 : Wsk0;
    __half* WcT = pair ? g_WcT1 : g_WcT0;
    int d = t & 127, half = t >> 7;
    float acc[8] = {};
    for (int m0 = 0; m0 < 128; m0 += 64) {
        __syncthreads();
        for (int i = t; i < 64 * 128; i += 256) {
            int mm = i >> 7, dd = i & 127;
            sSk[i] = Wsk[((m0 + mm) * ADIM + a) * 128 + dd];
        }
        for (int i = t; i < 16 * 64; i += 256) {
            int cc = i >> 6, mm = i & 63;
            sWl[i] = Wl[(c0 + cc) * 128 + m0 + mm];
        }
        __syncthreads();
        #pragma unroll 8
        for (int m = 0; m < 64; m++) {
            float sk = sSk[m * 128 + d];
            #pragma unroll
            for (int j = 0; j < 8; j++) {
                int cc = half + 2 * j;
                acc[j] = fmaf(sWl[cc * 64 + m], sk, acc[j]);
            }
        }
    }
    #pragma unroll
    for (int j = 0; j < 8; j++) {
        int c = c0 + half + 2 * j;   // k index 0..255
        WcT[(a * 128 + d) * 256 + c] = __float2half_rn(acc[j]);
    }
}

// ---------------- edge aggregation: sequential CSR streams, pipelined ----------------
__global__ __launch_bounds__(128) void k_agg() {
    int t = threadIdx.x;
    int n = blockIdx.x * 2 + (t >> 6);        // N_NODES even
    int c2 = t & 63;                          // channels 2*c2, 2*c2+1
    int beg = g_off[n], end = g_off[n + 1];

    float2 ms1 = {0, 0}, ms2 = {0, 0};
    float2 mv10 = {0, 0}, mv11 = {0, 0}, mv12 = {0, 0};
    float2 mv20 = {0, 0}, mv21 = {0, 0}, mv22 = {0, 0};

    int sjn = 0; float4 yn = {0, 0, 0, 0};
    if (beg < end) { sjn = g_scsr[beg]; yn = g_eacsr[beg]; }

    for (int p = beg; p < end; p++) {
        int sj = sjn; float4 y = yn;
        if (p + 1 < end) { sjn = g_scsr[p + 1]; yn = g_eacsr[p + 1]; }

        const __half2* tw = (const __half2*)(g_tpw16 + (size_t)p * 512);
        float2 ws1 = __half22float2(tw[c2]);
        float2 ws2 = __half22float2(tw[64 + c2]);
        float2 wv1 = __half22float2(tw[128 + c2]);
        float2 wv2 = __half22float2(tw[192 + c2]);
        float2 sv = *(const float2*)&g_s[sj * 128 + 2 * c2];
        const float* vb = &g_v[sj * 384 + 2 * c2];
        float2 v0 = *(const float2*)(vb);
        float2 v1 = *(const float2*)(vb + 128);
        float2 v2 = *(const float2*)(vb + 256);

        ms1.x = fmaf(ws1.x * sv.x, y.x, ms1.x);
        ms1.y = fmaf(ws1.y * sv.y, y.x, ms1.y);
        float dx = v0.x * y.y + v1.x * y.z + v2.x * y.w;
        float dy = v0.y * y.y + v1.y * y.z + v2.y * y.w;
        ms2.x = fmaf(ws2.x, dx, ms2.x);
        ms2.y = fmaf(ws2.y, dy, ms2.y);
        float a1x = wv1.x * sv.x, a1y = wv1.y * sv.y;
        mv10.x = fmaf(a1x, y.y, mv10.x); mv10.y = fmaf(a1y, y.y, mv10.y);
        mv11.x = fmaf(a1x, y.z, mv11.x); mv11.y = fmaf(a1y, y.z, mv11.y);
        mv12.x = fmaf(a1x, y.w, mv12.x); mv12.y = fmaf(a1y, y.w, mv12.y);
        float a2x = wv2.x * y.x, a2y = wv2.y * y.x;
        mv20.x = fmaf(a2x, v0.x, mv20.x); mv20.y = fmaf(a2y, v0.y, mv20.y);
        mv21.x = fmaf(a2x, v1.x, mv21.x); mv21.y = fmaf(a2y, v1.y, mv21.y);
        mv22.x = fmaf(a2x, v2.x, mv22.x); mv22.y = fmaf(a2y, v2.y, mv22.y);
    }

    __half2* M = (__half2*)g_M16;
    const int PL2 = N_NODES * 128;
    M[n * 128 + c2]            = __floats2half2_rn(ms1.x, ms1.y);
    M[n * 128 + 64 + c2]       = __floats2half2_rn(ms2.x * INV_SQRT3, ms2.y * INV_SQRT3);
    M[PL2 + n * 128 + c2]      = __floats2half2_rn(mv10.x, mv10.y);
    M[PL2 + n * 128 + 64 + c2] = __floats2half2_rn(mv20.x, mv20.y);
    M[2*PL2 + n * 128 + c2]      = __floats2half2_rn(mv11.x, mv11.y);
    M[2*PL2 + n * 128 + 64 + c2] = __floats2half2_rn(mv21.x, mv21.y);
    M[3*PL2 + n * 128 + c2]      = __floats2half2_rn(mv12.x, mv12.y);
    M[3*PL2 + n * 128 + 64 + c2] = __floats2half2_rn(mv22.x, mv22.y);
}

// ---------------- class-batched output GEMM via fp16 mma (verified R14, unchanged) ----
__global__ __launch_bounds__(128) void k_final(float* __restrict__ out) {
    __shared__ __align__(16) unsigned sA[64 * 36];
    __shared__ __align__(16) unsigned sB[128 * 36];
    __shared__ int sN[64];
    unsigned sbA = smem_u32(sA), sbB = smem_u32(sB);

    int t = threadIdx.x, lane = t & 31, wid = t >> 5;
    int comp = blockIdx.y;
    int row0 = blockIdx.x * 64;
    if (row0 >= g_pcoff[ADIM]) return;
    int a = 0;
    while (row0 >= g_pcoff[a + 1]) a++;

    if (t < 64) sN[t] = g_clistp[row0 + t];
    __syncthreads();

    const uint4* M = (const uint4*)g_M16 + (size_t)comp * (N_NODES * 32);
    const uint4* B = (const uint4*)(comp == 0 ? g_WcT0 : g_WcT1) + a * 128 * 32;

    int g = lane >> 2, q = lane & 3;
    int m0 = (wid >> 1) * 32;
    int n0 = (wid & 1) * 64;
    unsigned aoff = (unsigned)((lane & 15) * 144 + ((lane >> 4) << 4)) + m0 * 144;
    unsigned boff = (unsigned)((((lane >> 4) << 3) + (lane & 7)) * 144 + (((lane >> 3) & 1) << 4)) + n0 * 144;
    unsigned Ab = sbA + aoff;
    unsigned Bb = sbB + boff;

    float acc[2][8][4];
    #pragma unroll
    for (int mt = 0; mt < 2; mt++)
        #pragma unroll
        for (int nt = 0; nt < 8; nt++)
            #pragma unroll
            for (int j = 0; j < 4; j++) acc[mt][nt][j] = 0.f;

    for (int kc = 0; kc < 4; kc++) {
        __syncthreads();
        for (int i = t; i < 64 * 8; i += 128) {
            int row = i >> 3, u = i & 7;
            int node = sN[row];
            uint4 v = make_uint4(0, 0, 0, 0);
            if (node >= 0) v = M[node * 32 + kc * 8 + u];
            *(uint4*)&sA[row * 36 + u * 4] = v;
        }
        for (int i = t; i < 128 * 8; i += 128) {
            int col = i >> 3, u = i & 7;
            uint4 v = B[col * 32 + kc * 8 + u];
            *(uint4*)&sB[col * 36 + u * 4] = v;
        }
        __syncthreads();

        #pragma unroll
        for (int kt = 0; kt < 4; kt++) {
            unsigned af[2][4];
            #pragma unroll
            for (int mt = 0; mt < 2; mt++)
                LDSM4(af[mt][0], af[mt][1], af[mt][2], af[mt][3], Ab + mt * 2304 + kt * 32);
            #pragma unroll
            for (int j = 0; j < 4; j++) {
                unsigned bf[4];
                LDSM4(bf[0], bf[1], bf[2], bf[3], Bb + j * 2304 + kt * 32);
                #pragma unroll
                for (int h = 0; h < 2; h++) {
                    int nt = j * 2 + h;
                    #pragma unroll
                    for (int mt = 0; mt < 2; mt++)
                        MMA16816(acc[mt][nt], af[mt][0], af[mt][1], af[mt][2], af[mt][3],
                                 bf[h * 2], bf[h * 2 + 1]);
                }
            }
        }
    }

    #pragma unroll
    for (int mt = 0; mt < 2; mt++) {
        int r = m0 + mt * 16 + g;
        int nodeA = sN[r], nodeB = sN[r + 8];
        #pragma unroll
        for (int nt = 0; nt < 8; nt++) {
            int col = n0 + nt * 8 + q * 2;
            if (comp == 0) {
                if (nodeA >= 0)
                    *(float2*)&out[nodeA * 512 + col] =
                        make_float2(acc[mt][nt][0] * OUT_SCALE, acc[mt][nt][1] * OUT_SCALE);
                if (nodeB >= 0)
                    *(float2*)&out[nodeB * 512 + col] =
                        make_float2(acc[mt][nt][2] * OUT_SCALE, acc[mt][nt][3] * OUT_SCALE);
            } else {
                int cb = 128 + (comp - 1);
                if (nodeA >= 0) {
                    out[nodeA * 512 + cb + col * 3]       = acc[mt][nt][0] * OUT_SCALE;
                    out[nodeA * 512 + cb + (col + 1) * 3] = acc[mt][nt][1] * OUT_SCALE;
                }
                if (nodeB >= 0) {
                    out[nodeB * 512 + cb + col * 3]       = acc[mt][nt][2] * OUT_SCALE;
                    out[nodeB * 512 + cb + (col + 1) * 3] = acc[mt][nt][3] * OUT_SCALE;
                }
            }
        }
    }
}

// ---------------- launch ----------------
extern "C" void kernel_launch(void* const* d_in, const int* in_sizes, int n_in,
                              void* d_out, int out_size) {
    const float* node_attrs = (const float*)d_in[0];
    const float* node_feats = (const float*)d_in[1];
    const float* edge_attrs = (const float*)d_in[2];
    const float* edge_feats = (const float*)d_in[3];
    const int*   edge_index = (const int*)d_in[4];
    const float* W_up0  = (const float*)d_in[5];
    const float* W_up1  = (const float*)d_in[6];
    const float* W_mlp1 = (const float*)d_in[7];
    const float* W_mlp2 = (const float*)d_in[8];
    const float* W_mlp3 = (const float*)d_in[9];
    const float* W_mlp4 = (const float*)d_in[10];
    const float* W_lin0 = (const float*)d_in[11];
    const float* W_lin1 = (const float*)d_in[12];
    const float* W_skip0 = (const float*)d_in[13];
    const float* W_skip1 = (const float*)d_in[14];
    float* out = (float*)d_out;

    const int* sender = edge_index;            // row 0
    const int* recv   = edge_index + N_EDGES;  // row 1

    // slot 4 = k_mlp (ncu capture target this round)
    k_w4t<<<144, 256>>>(W_mlp4, W_mlp2, W_mlp3);                     // 1
    k_cls<<<(NPAD + 255) / 256, 256>>>(node_attrs);                  // 2
    k_count<<<N_EDGES / 256, 256>>>(recv);                           // 3
    k_mlp<<<N_EDGES / 64, 128>>>(edge_feats, W_mlp1);                // 4  (tensor core)
    k_scan<<<1, 1024>>>();                                           // 5
    k_fill<<<N_EDGES / 256, 256>>>(recv, sender, edge_attrs);        // 6
    k_tpw<<<N_EDGES / 64, 128>>>();                                  // 7  (tensor core)
    k_sv<<<dim3((N_NODES + 31) / 32, 2), 256>>>(node_feats, W_up0, W_up1); // 8
    k_wc<<<dim3(16, ADIM, 2), 256>>>(W_lin0, W_lin1, W_skip0, W_skip1); // 9
    k_agg<<<N_NODES / 2, 128>>>();                                   // 10
    k_final<<<dim3((NPAD + 63) / 64, 4), 128>>>(out);                // 11 (tensor core)
}